// round 7
// baseline (speedup 1.0000x reference)
#include <cuda_runtime.h>
#include <math.h>

#define S     610
#define SP    640          // padded K / state dim
#define E     126
#define BATCH 32
#define TLEN  2048
#define NREG  5000
#define JG    20           // column groups (20*32 = 640)
#define BG    4            // batch groups (4*8 = 32)
#define NC    32           // cols per block
#define NB    8            // batches per block
#define BMP   127          // Bm smem row stride (odd)

// ---------------- persistent device scratch ----------------
__device__ float    g_alpha[2][BATCH][SP];    // ping-pong unnormalized alpha
__device__ float    g_zpart[2][BATCH][JG];    // partial row sums
__device__ double   g_ll[BATCH];
__device__ unsigned g_bar[BG];                // monotonic barrier counters
__device__ int      g_obs[BATCH * TLEN];

// ---------------- helpers ----------------
__device__ __forceinline__ float warp_sum(float v) {
    v += __shfl_xor_sync(0xffffffffu, v, 16);
    v += __shfl_xor_sync(0xffffffffu, v, 8);
    v += __shfl_xor_sync(0xffffffffu, v, 4);
    v += __shfl_xor_sync(0xffffffffu, v, 2);
    v += __shfl_xor_sync(0xffffffffu, v, 1);
    return v;
}

__device__ __forceinline__ float2 ffma2(float2 a, float2 b, float2 c) {
    float2 d;
    asm("{\n\t"
        ".reg .b64 ra, rb, rc, rd;\n\t"
        "mov.b64 ra, {%2,%3};\n\t"
        "mov.b64 rb, {%4,%5};\n\t"
        "mov.b64 rc, {%6,%7};\n\t"
        "fma.rn.f32x2 rd, ra, rb, rc;\n\t"
        "mov.b64 {%0,%1}, rd;\n\t"
        "}"
        : "=f"(d.x), "=f"(d.y)
        : "f"(a.x), "f"(a.y), "f"(b.x), "f"(b.y), "f"(c.x), "f"(c.y));
    return d;
}

__device__ __forceinline__ unsigned ld_cg_u32(const unsigned* p) {
    unsigned v;
    asm volatile("ld.global.cg.u32 %0, [%1];" : "=r"(v) : "l"(p));
    return v;
}
__device__ __forceinline__ float ld_cg_f32(const float* p) {
    float v;
    asm volatile("ld.global.cg.f32 %0, [%1];" : "=f"(v) : "l"(p));
    return v;
}
__device__ __forceinline__ float4 ld_cg_f128(const float4* p) {
    float4 v;
    asm volatile("ld.global.cg.v4.f32 {%0,%1,%2,%3}, [%4];"
                 : "=f"(v.x), "=f"(v.y), "=f"(v.z), "=f"(v.w) : "l"(p));
    return v;
}
__device__ __forceinline__ void st_cg_f32(float* p, float v) {
    asm volatile("st.global.cg.f32 [%0], %1;" :: "l"(p), "f"(v));
}

// barrier among the JG blocks of one batch group (monotonic counter)
__device__ __forceinline__ void grid_bar(int bg, unsigned target) {
    __syncthreads();
    if (threadIdx.x == 0) {
        __threadfence();
        atomicAdd(&g_bar[bg], 1u);
        while (ld_cg_u32(&g_bar[bg]) < target) { }
        __threadfence();
    }
    __syncthreads();
}

// ---------------- kernel 1: reset (graph-replay safety) ----------------
__global__ void reset_kernel() {
    if (threadIdx.x < BG) g_bar[threadIdx.x] = 0u;
}

// ---------------- kernel 2: one-hot -> index ----------------
__global__ void obs_kernel(const float* __restrict__ inputs) {
    int wid = threadIdx.x >> 5, lane = threadIdx.x & 31;
    int idx = blockIdx.x * 8 + wid;             // one warp per (b,t) row
    if (idx >= BATCH * TLEN) return;
    const float* row = inputs + (size_t)idx * E;
    int best = 0;
#pragma unroll
    for (int m = 0; m < 4; m++) {
        int e = lane + 32 * m;
        if (e < E && row[e] > 0.5f) best = e;
    }
#pragma unroll
    for (int d = 16; d; d >>= 1)
        best = max(best, __shfl_xor_sync(0xffffffffu, best, d));
    if (lane == 0) g_obs[idx] = best;
}

// ---------------- kernel 3: persistent scaled forward ----------------
// grid (20, 4), 256 threads. Block = 32 cols x 8 batches x full K.
// smem layout (bytes):
//   A2s  float2[320][32]   @      0   (81920)  A2[kp][j] = (A[2kp][col], A[2kp+1][col])
//   al4  float4[8][160]    @  81920   (20480)  staged alpha (pairs of k-pairs)
//   Bms  float [32][127]   @ 102400   (16256)
//   pacc float2[8][8][32]  @ 118656   (16384)  per-warp k-partials [w][b][j]
//   zsm  float [8]         @ 135040
#define SM_BYTES 135072

__global__ void __launch_bounds__(256, 1)
hmm_kernel(const float* __restrict__ Ag, const float* __restrict__ Bmg,
           const float* __restrict__ Ig) {
    extern __shared__ char sm[];
    float2* A2s  = (float2*)(sm);
    float4* al4  = (float4*)(sm + 81920);
    float*  Bms  = (float*)(sm + 102400);
    float2* pacc = (float2*)(sm + 118656);
    float*  zsm  = (float*)(sm + 135040);

    const int tid  = threadIdx.x;
    const int wid  = tid >> 5, lane = tid & 31;
    const int jg   = blockIdx.x;       // 0..19
    const int bg   = blockIdx.y;       // 0..3
    const int b    = bg * NB + wid;    // this warp's batch
    const int col0 = jg * NC;
    const int col  = col0 + lane;

    // ---- prologue: stage A column slice (zero-padded) and Bm slice ----
    for (int idx = tid; idx < 320 * 32; idx += 256) {
        int kp = idx >> 5, j = idx & 31;
        int k0 = 2 * kp, k1 = 2 * kp + 1, c = col0 + j;
        float x = 0.f, y = 0.f;
        if (c < S) {
            if (k0 < S) x = Ag[(size_t)k0 * S + c];
            if (k1 < S) y = Ag[(size_t)k1 * S + c];
        }
        A2s[idx] = make_float2(x, y);
    }
    for (int idx = tid; idx < NC * BMP; idx += 256) {
        int j = idx / BMP, e = idx % BMP;
        int c = col0 + j;
        Bms[idx] = (c < S && e < E) ? Bmg[(size_t)c * E + e] : 0.f;
    }
    __syncthreads();

    // ---- t = 0: alpha0 = I * em0 (unnormalized) ----
    {
        int o = g_obs[b * TLEN + 0];
        float iv = (col < S) ? Ig[col] : 0.f;
        float v = iv * Bms[lane * BMP + o];
        st_cg_f32(&g_alpha[0][b][col], v);
        float zp = warp_sum(v);
        if (lane == 0) st_cg_f32(&g_zpart[0][b][jg], zp);
    }
    grid_bar(bg, JG * 1u);

    double ll_acc = 0.0;

    for (int t = 1; t < TLEN; ++t) {
        const int cur = t & 1, prev = cur ^ 1;

        // phase a: z_{t-1} per batch (warp wid -> batch b)
        {
            float v = (lane < JG) ? ld_cg_f32(&g_zpart[prev][b][lane]) : 0.f;
            float z = warp_sum(v);
            if (lane == 0) {
                zsm[wid] = 1.0f / z;
                if (jg == 0) ll_acc += log((double)z);
            }
        }
        // phase b: stage unnormalized alpha_{t-1} for our 8 batches
        for (int i = tid; i < NB * 160; i += 256) {
            int bb = i / 160, kp2 = i % 160;
            al4[i] = ld_cg_f128((const float4*)&g_alpha[prev][bg * NB + bb][kp2 * 4]);
        }
        __syncthreads();

        // phase c: warp wid handles k-pairs [wid*40, wid*40+40)
        float2 acc[NB];
#pragma unroll
        for (int bb = 0; bb < NB; bb++) acc[bb] = make_float2(0.f, 0.f);
        const int q0 = wid * 20;
#pragma unroll 4
        for (int q = 0; q < 20; q++) {
            int kp2 = q0 + q;
            float2 a0 = A2s[(2 * kp2) * 32 + lane];
            float2 a1 = A2s[(2 * kp2 + 1) * 32 + lane];
#pragma unroll
            for (int bb = 0; bb < NB; bb++) {
                float4 av = al4[bb * 160 + kp2];
                acc[bb] = ffma2(make_float2(av.x, av.y), a0, acc[bb]);
                acc[bb] = ffma2(make_float2(av.z, av.w), a1, acc[bb]);
            }
        }
#pragma unroll
        for (int bb = 0; bb < NB; bb++)
            pacc[(wid * NB + bb) * 32 + lane] = acc[bb];
        __syncthreads();

        // phase d: reduce partials, apply em * (1/z_{t-1}), write alpha_t
        {
            float s = 0.f;
#pragma unroll
            for (int w2 = 0; w2 < 8; w2++) {
                float2 p = pacc[(w2 * NB + wid) * 32 + lane];
                s += p.x + p.y;
            }
            int o = g_obs[b * TLEN + t];
            float val = s * Bms[lane * BMP + o] * zsm[wid];
            st_cg_f32(&g_alpha[cur][b][col], val);
            float zp = warp_sum(val);
            if (lane == 0) st_cg_f32(&g_zpart[cur][b][jg], zp);
        }
        grid_bar(bg, JG * (unsigned)(t + 1));
    }

    // final normalizer z_{T-1} and write ll
    if (jg == 0) {
        float v = (lane < JG) ? ld_cg_f32(&g_zpart[1][b][lane]) : 0.f; // T-1=2047 odd -> buf 1
        float z = warp_sum(v);
        if (lane == 0) {
            ll_acc += log((double)z);
            g_ll[b] = ll_acc;
        }
    }
}

// ---------------- kernel 4: finalize ----------------
__global__ void finalize_kernel(const float* __restrict__ Ag,
                                const int* __restrict__ rf,
                                const int* __restrict__ rt,
                                float* __restrict__ out) {
    __shared__ double red[256];
    int tid = threadIdx.x;
    double s = 0.0;
    for (int i = tid; i < NREG; i += 256) {
        float a = Ag[(size_t)rf[i] * S + rt[i]];
        s += log1p(-(double)a);
    }
    red[tid] = s;
    __syncthreads();
    for (int st = 128; st; st >>= 1) {
        if (tid < st) red[tid] += red[tid + st];
        __syncthreads();
    }
    if (tid == 0) {
        double ll = 0.0;
        for (int b = 0; b < BATCH; b++) ll += g_ll[b];
        double loss = -(ll / (double)BATCH) - 4.0 * (red[0] / (double)NREG);
        out[0] = (float)loss;
    }
}

// ---------------- launcher ----------------
extern "C" void kernel_launch(void* const* d_in, const int* in_sizes, int n_in,
                              void* d_out, int out_size) {
    const float* inputs = (const float*)d_in[0];   // [32,2048,126]
    const float* A      = (const float*)d_in[1];   // [610,610]
    const float* Bm     = (const float*)d_in[2];   // [610,126]
    const float* I      = (const float*)d_in[3];   // [610]
    const int*   rf     = (const int*)d_in[4];     // [5000]
    const int*   rt     = (const int*)d_in[5];     // [5000]
    float* out = (float*)d_out;

    cudaFuncSetAttribute(hmm_kernel,
                         cudaFuncAttributeMaxDynamicSharedMemorySize, SM_BYTES);

    reset_kernel<<<1, 32>>>();
    obs_kernel<<<(BATCH * TLEN) / 8, 256>>>(inputs);
    dim3 grid(JG, BG);
    hmm_kernel<<<grid, 256, SM_BYTES>>>(A, Bm, I);
    finalize_kernel<<<1, 256>>>(A, rf, rt, out);
}

// round 8
// speedup vs baseline: 1.4671x; 1.4671x over previous
#include <cuda_runtime.h>
#include <math.h>

#define S     610
#define SP    640          // padded state dim
#define E     126
#define BATCH 32
#define TLEN  2048
#define NREG  5000
#define JG    20           // column groups (20*32 = 640)
#define BG    4            // batch groups (4*8 = 32)
#define NC    32           // cols per block
#define NB    8            // batches per block
#define BMP   127          // Bm smem row stride (odd -> conflict-free gather)

// ---------------- persistent device scratch ----------------
__device__ float    g_alpha[2][BATCH][SP];    // ping-pong unnormalized alpha (padding stays 0)
__device__ float    g_zs[BATCH * TLEN];       // per-step normalizers, logs taken in finalize
__device__ double   g_part[96];               // finalize partials
__device__ unsigned g_bar[BG];                // monotonic barrier counters (per batch group)
__device__ int      g_obs[BATCH * TLEN];

// ---------------- helpers ----------------
__device__ __forceinline__ float warp_sum(float v) {
    v += __shfl_xor_sync(0xffffffffu, v, 16);
    v += __shfl_xor_sync(0xffffffffu, v, 8);
    v += __shfl_xor_sync(0xffffffffu, v, 4);
    v += __shfl_xor_sync(0xffffffffu, v, 2);
    v += __shfl_xor_sync(0xffffffffu, v, 1);
    return v;
}

__device__ __forceinline__ float2 ffma2(float2 a, float2 b, float2 c) {
    float2 d;
    asm("{\n\t"
        ".reg .b64 ra, rb, rc, rd;\n\t"
        "mov.b64 ra, {%2,%3};\n\t"
        "mov.b64 rb, {%4,%5};\n\t"
        "mov.b64 rc, {%6,%7};\n\t"
        "fma.rn.f32x2 rd, ra, rb, rc;\n\t"
        "mov.b64 {%0,%1}, rd;\n\t"
        "}"
        : "=f"(d.x), "=f"(d.y)
        : "f"(a.x), "f"(a.y), "f"(b.x), "f"(b.y), "f"(c.x), "f"(c.y));
    return d;
}

__device__ __forceinline__ unsigned ld_acq_u32(const unsigned* p) {
    unsigned v;
    asm volatile("ld.acquire.gpu.global.u32 %0, [%1];" : "=r"(v) : "l"(p));
    return v;
}
__device__ __forceinline__ void red_release_add(unsigned* p) {
    asm volatile("red.release.gpu.global.add.u32 [%0], 1;" :: "l"(p));
}
__device__ __forceinline__ float4 ld_cg_f128(const float4* p) {
    float4 v;
    asm volatile("ld.global.cg.v4.f32 {%0,%1,%2,%3}, [%4];"
                 : "=f"(v.x), "=f"(v.y), "=f"(v.z), "=f"(v.w) : "l"(p));
    return v;
}
__device__ __forceinline__ void st_cg_f32(float* p, float v) {
    asm volatile("st.global.cg.f32 [%0], %1;" :: "l"(p), "f"(v));
}

// ---------------- kernel 1: reset (graph-replay safety) ----------------
__global__ void reset_kernel() {
    if (threadIdx.x < BG) g_bar[threadIdx.x] = 0u;
}

// ---------------- kernel 2: one-hot -> index ----------------
__global__ void obs_kernel(const float* __restrict__ inputs) {
    int wid = threadIdx.x >> 5, lane = threadIdx.x & 31;
    int idx = blockIdx.x * 8 + wid;             // one warp per (b,t) row
    if (idx >= BATCH * TLEN) return;
    const float* row = inputs + (size_t)idx * E;
    int best = 0;
#pragma unroll
    for (int m = 0; m < 4; m++) {
        int e = lane + 32 * m;
        if (e < E && row[e] > 0.5f) best = e;
    }
#pragma unroll
    for (int d = 16; d; d >>= 1)
        best = max(best, __shfl_xor_sync(0xffffffffu, best, d));
    if (lane == 0) g_obs[idx] = best;
}

// ---------------- kernel 3: persistent scaled forward ----------------
// grid (20, 4), 256 threads. Block = 32 cols x 8 batches x full K (k-split by warp).
// smem (bytes):
//   A4s  float4[160][32] @      0  (81920)  A4s[kp][j] = A[4kp..4kp+3][col0+j], zero-padded
//   al4  float4[8][160]  @  81920  (20480)  staged alpha_{t-1} for the 8 batches
//   Bms  float [32][127] @ 102400  (16256)
//   pacc float2[8][8][32]@ 118656  (16384)  per-warp k-partials [w][b][j]
#define SM_BYTES 135040

__global__ void __launch_bounds__(256, 1)
hmm_kernel(const float* __restrict__ Ag, const float* __restrict__ Bmg,
           const float* __restrict__ Ig) {
    extern __shared__ char sm[];
    float4* A4s  = (float4*)(sm);
    float4* al4  = (float4*)(sm + 81920);
    float*  Bms  = (float*)(sm + 102400);
    float2* pacc = (float2*)(sm + 118656);

    const int tid  = threadIdx.x;
    const int wid  = tid >> 5, lane = tid & 31;
    const int jg   = blockIdx.x;       // 0..19
    const int bg   = blockIdx.y;       // 0..3
    const int b    = bg * NB + wid;    // this warp's batch
    const int col0 = jg * NC;
    const int col  = col0 + lane;

    // ---- prologue: stage A column slice (float4 k-packed, zero-padded) + Bm slice ----
    for (int idx = tid; idx < 160 * 32; idx += 256) {
        int kp = idx >> 5, j = idx & 31, c = col0 + j;
        float4 v = make_float4(0.f, 0.f, 0.f, 0.f);
        if (c < S) {
            int k0 = kp * 4;
            if (k0     < S) v.x = Ag[(size_t)(k0    ) * S + c];
            if (k0 + 1 < S) v.y = Ag[(size_t)(k0 + 1) * S + c];
            if (k0 + 2 < S) v.z = Ag[(size_t)(k0 + 2) * S + c];
            if (k0 + 3 < S) v.w = Ag[(size_t)(k0 + 3) * S + c];
        }
        A4s[idx] = v;
    }
    for (int idx = tid; idx < NC * BMP; idx += 256) {
        int j = idx / BMP, e = idx % BMP;
        int c = col0 + j;
        Bms[idx] = (c < S && e < E) ? Bmg[(size_t)c * E + e] : 0.f;
    }
    __syncthreads();

    // ---- t = 0: alpha0 = I * em0 (unnormalized; padding cols write 0) ----
    {
        int o = g_obs[b * TLEN + 0];
        float iv = (col < S) ? Ig[col] : 0.f;
        float v0 = iv * Bms[lane * BMP + o];
        st_cg_f32(&g_alpha[0][b][col], v0);
    }
    __syncthreads();
    if (tid == 0) red_release_add(&g_bar[bg]);

    const int q0 = wid * 20;   // this warp's k-pair range (covers k = q0*4 .. q0*4+79)

    for (int t = 1; t < TLEN; ++t) {
        const int cur = t & 1, prev = cur ^ 1;

        // wait: all 20 blocks of this batch group have written alpha_{t-1}
        if (tid == 0) {
            while (ld_acq_u32(&g_bar[bg]) < JG * (unsigned)t) { }
        }
        __syncthreads();

        int o = g_obs[b * TLEN + t];   // prefetch (uniform per warp, L1-resident)

        // stage alpha_{t-1} for our 8 batches (1280 float4 from L2, 5 per thread)
        for (int i = tid; i < NB * 160; i += 256) {
            int bb = i / 160, kp = i % 160;
            al4[i] = ld_cg_f128((const float4*)&g_alpha[prev][bg * NB + bb][kp * 4]);
        }
        __syncthreads();

        // z_{t-1} per batch, computed locally (identical fp32 order in every block)
        float zp = 0.f;
#pragma unroll
        for (int i = 0; i < 5; i++) {
            float4 v = al4[wid * 160 + lane + 32 * i];
            zp += (v.x + v.y) + (v.z + v.w);
        }
        float z  = warp_sum(zp);
        float rz = 1.0f / z;
        if (jg == 0 && lane == 0) st_cg_f32(&g_zs[b * TLEN + (t - 1)], z);

        // k-split matvec: warp wid handles k-pairs [q0, q0+20) for all 8 batches
        float2 acc[NB];
#pragma unroll
        for (int bb = 0; bb < NB; bb++) acc[bb] = make_float2(0.f, 0.f);
#pragma unroll 5
        for (int q = 0; q < 20; q++) {
            int kp = q0 + q;
            float4 a4 = A4s[kp * 32 + lane];
#pragma unroll
            for (int bb = 0; bb < NB; bb++) {
                float4 av = al4[bb * 160 + kp];
                acc[bb] = ffma2(make_float2(av.x, av.y), make_float2(a4.x, a4.y), acc[bb]);
                acc[bb] = ffma2(make_float2(av.z, av.w), make_float2(a4.z, a4.w), acc[bb]);
            }
        }
#pragma unroll
        for (int bb = 0; bb < NB; bb++)
            pacc[(wid * NB + bb) * 32 + lane] = acc[bb];
        __syncthreads();

        // reduce k-partials, apply em * (1/z_{t-1}), write alpha_t
        {
            float s = 0.f;
#pragma unroll
            for (int w2 = 0; w2 < 8; w2++) {
                float2 p = pacc[(w2 * NB + wid) * 32 + lane];
                s += p.x + p.y;
            }
            float val = s * Bms[lane * BMP + o] * rz;
            st_cg_f32(&g_alpha[cur][b][col], val);
        }
        __syncthreads();
        if (tid == 0) red_release_add(&g_bar[bg]);
    }

    // epilogue: z_{T-1} (T-1 = 2047 -> buffer 1)
    if (jg == 0) {
        if (tid == 0) {
            while (ld_acq_u32(&g_bar[bg]) < JG * (unsigned)TLEN) { }
        }
        __syncthreads();
        float zp = 0.f;
#pragma unroll
        for (int i = 0; i < 5; i++) {
            float4 v = ld_cg_f128((const float4*)&g_alpha[1][b][(lane + 32 * i) * 4]);
            zp += (v.x + v.y) + (v.z + v.w);
        }
        float z = warp_sum(zp);
        if (lane == 0) st_cg_f32(&g_zs[b * TLEN + (TLEN - 1)], z);
    }
}

// ---------------- kernel 4a: parallel log sums ----------------
// blocks 0..63: logs of 1024 z values each; blocks 64..95: regularizer terms
__global__ void finalize1_kernel(const float* __restrict__ Ag,
                                 const int* __restrict__ rf,
                                 const int* __restrict__ rt) {
    __shared__ double red[256];
    int blk = blockIdx.x, tid = threadIdx.x;
    double s = 0.0;
    if (blk < 64) {
        const float* z = g_zs + blk * 1024;
        for (int i = tid; i < 1024; i += 256)
            s += (double)logf(z[i]);
    } else {
        int idx = (blk - 64) * 256 + tid;
        if (idx < NREG) {
            float a = Ag[(size_t)rf[idx] * S + rt[idx]];
            s = (double)log1pf(-a);
        }
    }
    red[tid] = s;
    __syncthreads();
    for (int st = 128; st; st >>= 1) {
        if (tid < st) red[tid] += red[tid + st];
        __syncthreads();
    }
    if (tid == 0) g_part[blk] = red[0];
}

// ---------------- kernel 4b: combine ----------------
__global__ void finalize2_kernel(float* __restrict__ out) {
    if (threadIdx.x == 0) {
        double ll = 0.0, rg = 0.0;
        for (int i = 0; i < 64; i++) ll += g_part[i];
        for (int i = 64; i < 96; i++) rg += g_part[i];
        double loss = -(ll / (double)BATCH) - 4.0 * (rg / (double)NREG);
        out[0] = (float)loss;
    }
}

// ---------------- launcher ----------------
extern "C" void kernel_launch(void* const* d_in, const int* in_sizes, int n_in,
                              void* d_out, int out_size) {
    const float* inputs = (const float*)d_in[0];   // [32,2048,126]
    const float* A      = (const float*)d_in[1];   // [610,610]
    const float* Bm     = (const float*)d_in[2];   // [610,126]
    const float* I      = (const float*)d_in[3];   // [610]
    const int*   rf     = (const int*)d_in[4];     // [5000]
    const int*   rt     = (const int*)d_in[5];     // [5000]
    float* out = (float*)d_out;

    cudaFuncSetAttribute(hmm_kernel,
                         cudaFuncAttributeMaxDynamicSharedMemorySize, SM_BYTES);

    reset_kernel<<<1, 32>>>();
    obs_kernel<<<(BATCH * TLEN) / 8, 256>>>(inputs);
    dim3 grid(JG, BG);
    hmm_kernel<<<grid, 256, SM_BYTES>>>(A, Bm, I);
    finalize1_kernel<<<96, 256>>>(A, rf, rt);
    finalize2_kernel<<<1, 32>>>(out);
}

// round 9
// speedup vs baseline: 2.0684x; 1.4099x over previous
#include <cuda_runtime.h>
#include <math.h>

#define S     610
#define SP    640          // padded state dim
#define E     126
#define BATCH 32
#define TLEN  2048
#define NREG  5000
#define JG    20           // column groups (20*32 = 640)
#define BG    4            // batch groups (4*8 = 32)
#define NC    32           // cols per block
#define NB    8            // batches per block
#define BMP   127          // Bm smem row stride (odd -> conflict-free gather)

typedef unsigned long long ull;

// ---------------- persistent device scratch ----------------
__device__ float  g_alpha[2][BATCH][SP];   // ping-pong unnormalized alpha (padding stays 0)
__device__ float  g_zs[BATCH * TLEN];      // per-step normalizers (logs in finalize)
__device__ double g_part[96];              // finalize partials
__device__ int    g_flag[BG][JG * 32];     // per-block progress flags, 128B apart
__device__ int    g_obsT[TLEN * BATCH];    // obs transposed [t][b]

// ---------------- helpers ----------------
__device__ __forceinline__ float warp_sum(float v) {
    v += __shfl_xor_sync(0xffffffffu, v, 16);
    v += __shfl_xor_sync(0xffffffffu, v, 8);
    v += __shfl_xor_sync(0xffffffffu, v, 4);
    v += __shfl_xor_sync(0xffffffffu, v, 2);
    v += __shfl_xor_sync(0xffffffffu, v, 1);
    return v;
}
__device__ __forceinline__ ull ffma2(ull a, ull b, ull c) {
    ull d;
    asm("fma.rn.f32x2 %0, %1, %2, %3;" : "=l"(d) : "l"(a), "l"(b), "l"(c));
    return d;
}
__device__ __forceinline__ ull packf2(float lo, float hi) {
    ull r;
    asm("mov.b64 %0, {%1, %2};" : "=l"(r) : "f"(lo), "f"(hi));
    return r;
}
__device__ __forceinline__ int ld_acq_s32(const int* p) {
    int v;
    asm volatile("ld.acquire.gpu.global.s32 %0, [%1];" : "=r"(v) : "l"(p));
    return v;
}
__device__ __forceinline__ void st_rel_s32(int* p, int v) {
    asm volatile("st.release.gpu.global.s32 [%0], %1;" :: "l"(p), "r"(v));
}
__device__ __forceinline__ void st_cg_f32(float* p, float v) {
    asm volatile("st.global.cg.f32 [%0], %1;" :: "l"(p), "f"(v));
}
__device__ __forceinline__ float4 ld_cg_f128(const float4* p) {
    float4 v;
    asm volatile("ld.global.cg.v4.f32 {%0,%1,%2,%3}, [%4];"
                 : "=f"(v.x), "=f"(v.y), "=f"(v.z), "=f"(v.w) : "l"(p));
    return v;
}
__device__ __forceinline__ void cp_async16(unsigned sa, const void* ga) {
    asm volatile("cp.async.cg.shared.global [%0], [%1], 16;" :: "r"(sa), "l"(ga) : "memory");
}
__device__ __forceinline__ void cp_async_wait_all() {
    asm volatile("cp.async.commit_group;\n\tcp.async.wait_group 0;" ::: "memory");
}

// ---------------- kernel 1: reset flags (graph-replay safety) ----------------
__global__ void reset_kernel() {
    int i = threadIdx.x;
    for (int k = i; k < BG * JG * 32; k += 256) ((int*)g_flag)[k] = 0;
}

// ---------------- kernel 2: one-hot -> index (transposed) ----------------
__global__ void obs_kernel(const float* __restrict__ inputs) {
    int wid = threadIdx.x >> 5, lane = threadIdx.x & 31;
    int idx = blockIdx.x * 8 + wid;             // one warp per (b,t) row
    if (idx >= BATCH * TLEN) return;
    const float* row = inputs + (size_t)idx * E;
    int best = 0;
#pragma unroll
    for (int m = 0; m < 4; m++) {
        int e = lane + 32 * m;
        if (e < E && row[e] > 0.5f) best = e;
    }
#pragma unroll
    for (int d = 16; d; d >>= 1)
        best = max(best, __shfl_xor_sync(0xffffffffu, best, d));
    if (lane == 0) {
        int b = idx / TLEN, t = idx % TLEN;
        g_obsT[t * BATCH + b] = best;
    }
}

// ---------------- kernel 3: persistent scaled forward ----------------
// grid (20, 4), 256 threads. Block = 32 cols x 8 batches; k split across warps.
// A lives in REGISTERS (80 floats = 40 b64 per thread). smem:
//   al2  ulonglong2[8*160] @     0  (20480)  alpha_{t-1} for the 8 batches
//   Bms  float[32*127]     @ 20480  (16256)
//   pacc float2[8*8*32]    @ 36736  (16384)  per-warp k-partials [w][b][j]
#define SM_BYTES 53120

__global__ void __launch_bounds__(256, 1)
hmm_kernel(const float* __restrict__ Ag, const float* __restrict__ Bmg,
           const float* __restrict__ Ig) {
    extern __shared__ char sm[];
    ulonglong2* al2 = (ulonglong2*)(sm);
    float*      Bms = (float*)(sm + 20480);
    float2*     pacc = (float2*)(sm + 36736);

    const int tid  = threadIdx.x;
    const int wid  = tid >> 5, lane = tid & 31;
    const int jg   = blockIdx.x;       // 0..19
    const int bg   = blockIdx.y;       // 0..3
    const int b    = bg * NB + wid;    // this warp's batch
    const int col0 = jg * NC;
    const int col  = col0 + lane;
    const int q0   = wid * 20;         // this warp's k-pair4 range

    const unsigned al2_sa = (unsigned)__cvta_generic_to_shared(al2);
    const char* aprev[2] = { (const char*)&g_alpha[0][bg * NB][0],
                             (const char*)&g_alpha[1][bg * NB][0] };

    // ---- prologue: A column slice into registers (zero-padded) ----
    ull au[40];
#pragma unroll
    for (int q = 0; q < 20; q++) {
        int k0 = (q0 + q) * 4;
        float x0 = 0.f, x1 = 0.f, x2 = 0.f, x3 = 0.f;
        if (col < S) {
            if (k0     < S) x0 = Ag[(size_t)(k0    ) * S + col];
            if (k0 + 1 < S) x1 = Ag[(size_t)(k0 + 1) * S + col];
            if (k0 + 2 < S) x2 = Ag[(size_t)(k0 + 2) * S + col];
            if (k0 + 3 < S) x3 = Ag[(size_t)(k0 + 3) * S + col];
        }
        au[2 * q]     = packf2(x0, x1);
        au[2 * q + 1] = packf2(x2, x3);
    }
    // Bm slice into smem
    for (int idx = tid; idx < NC * BMP; idx += 256) {
        int j = idx / BMP, e = idx % BMP;
        int c = col0 + j;
        Bms[idx] = (c < S && e < E) ? Bmg[(size_t)c * E + e] : 0.f;
    }
    __syncthreads();

    // ---- t = 0: alpha0 = I * em0 (unnormalized; padding cols write 0) ----
    {
        int o = g_obsT[0 * BATCH + b];
        float iv = (col < S) ? Ig[col] : 0.f;
        float v0 = iv * Bms[lane * BMP + o];
        st_cg_f32(&g_alpha[0][b][col], v0);
    }
    __syncthreads();
    if (tid == 0) st_rel_s32(&g_flag[bg][jg * 32], 1);

    int* const myflag = &g_flag[bg][jg * 32];
    const int* const pollflag = &g_flag[bg][lane * 32];

    for (int t = 1; t < TLEN; ++t) {
        const int cur = t & 1, prev = cur ^ 1;

        int o = g_obsT[t * BATCH + b];   // uniform per warp

        // ---- wait: all 20 blocks of this batch group have written alpha_{t-1} ----
        if (wid == 0) {
            while (true) {
                int f = (lane < JG) ? ld_acq_s32(pollflag) : 0x7fffffff;
                if (__all_sync(0xffffffffu, f >= t)) break;
            }
        }
        __syncthreads();

        // ---- stage alpha_{t-1} for our 8 batches: 1280 x 16B via cp.async ----
        {
            const char* src = aprev[prev];
#pragma unroll
            for (int j = 0; j < 5; j++) {
                int i = tid + 256 * j;
                cp_async16(al2_sa + (unsigned)i * 16u, src + (size_t)i * 16u);
            }
            cp_async_wait_all();
        }
        __syncthreads();

        // ---- k-split matvec: A in registers, alpha via smem broadcast ----
        ull acc[NB];
#pragma unroll
        for (int bb = 0; bb < NB; bb++) acc[bb] = 0ull;
#pragma unroll
        for (int q = 0; q < 20; q++) {
            int kp = q0 + q;
#pragma unroll
            for (int bb = 0; bb < NB; bb++) {
                ulonglong2 av = al2[bb * 160 + kp];
                acc[bb] = ffma2(av.x, au[2 * q],     acc[bb]);
                acc[bb] = ffma2(av.y, au[2 * q + 1], acc[bb]);
            }
        }
#pragma unroll
        for (int bb = 0; bb < NB; bb++) {
            float2 p;
            asm("mov.b64 {%0, %1}, %2;" : "=f"(p.x), "=f"(p.y) : "l"(acc[bb]));
            pacc[(wid * NB + bb) * 32 + lane] = p;
        }

        // ---- z_{t-1} for this warp's batch (identical order in every block) ----
        float zp = 0.f;
#pragma unroll
        for (int i = 0; i < 5; i++) {
            float4 v = ((const float4*)al2)[wid * 160 + lane + 32 * i];
            zp += (v.x + v.y) + (v.z + v.w);
        }
        float z  = warp_sum(zp);
        float rz = 1.0f / z;
        if (jg == 0 && lane == 0) st_cg_f32(&g_zs[b * TLEN + (t - 1)], z);

        __syncthreads();

        // ---- reduce k-partials, apply em * rz, write alpha_t ----
        {
            float s = 0.f;
#pragma unroll
            for (int w2 = 0; w2 < 8; w2++) {
                float2 p = pacc[(w2 * NB + wid) * 32 + lane];
                s += p.x + p.y;
            }
            float val = s * Bms[lane * BMP + o] * rz;
            st_cg_f32(&g_alpha[cur][b][col], val);
        }
        __syncthreads();
        if (tid == 0) st_rel_s32(myflag, t + 1);
    }

    // ---- epilogue: z_{T-1} (buffer 1) ----
    if (jg == 0) {
        if (wid == 0) {
            while (true) {
                int f = (lane < JG) ? ld_acq_s32(pollflag) : 0x7fffffff;
                if (__all_sync(0xffffffffu, f >= TLEN)) break;
            }
        }
        __syncthreads();
        float zp = 0.f;
#pragma unroll
        for (int i = 0; i < 5; i++) {
            float4 v = ld_cg_f128((const float4*)&g_alpha[1][b][(lane + 32 * i) * 4]);
            zp += (v.x + v.y) + (v.z + v.w);
        }
        float z = warp_sum(zp);
        if (lane == 0) st_cg_f32(&g_zs[b * TLEN + (TLEN - 1)], z);
    }
}

// ---------------- kernel 4a: parallel log sums ----------------
__global__ void finalize1_kernel(const float* __restrict__ Ag,
                                 const int* __restrict__ rf,
                                 const int* __restrict__ rt) {
    __shared__ double red[256];
    int blk = blockIdx.x, tid = threadIdx.x;
    double s = 0.0;
    if (blk < 64) {
        const float* z = g_zs + blk * 1024;
        for (int i = tid; i < 1024; i += 256)
            s += (double)logf(z[i]);
    } else {
        int idx = (blk - 64) * 256 + tid;
        if (idx < NREG) {
            float a = Ag[(size_t)rf[idx] * S + rt[idx]];
            s = (double)log1pf(-a);
        }
    }
    red[tid] = s;
    __syncthreads();
    for (int st = 128; st; st >>= 1) {
        if (tid < st) red[tid] += red[tid + st];
        __syncthreads();
    }
    if (tid == 0) g_part[blk] = red[0];
}

// ---------------- kernel 4b: combine ----------------
__global__ void finalize2_kernel(float* __restrict__ out) {
    if (threadIdx.x == 0) {
        double ll = 0.0, rg = 0.0;
        for (int i = 0; i < 64; i++) ll += g_part[i];
        for (int i = 64; i < 96; i++) rg += g_part[i];
        double loss = -(ll / (double)BATCH) - 4.0 * (rg / (double)NREG);
        out[0] = (float)loss;
    }
}

// ---------------- launcher ----------------
extern "C" void kernel_launch(void* const* d_in, const int* in_sizes, int n_in,
                              void* d_out, int out_size) {
    const float* inputs = (const float*)d_in[0];   // [32,2048,126]
    const float* A      = (const float*)d_in[1];   // [610,610]
    const float* Bm     = (const float*)d_in[2];   // [610,126]
    const float* I      = (const float*)d_in[3];   // [610]
    const int*   rf     = (const int*)d_in[4];     // [5000]
    const int*   rt     = (const int*)d_in[5];     // [5000]
    float* out = (float*)d_out;

    cudaFuncSetAttribute(hmm_kernel,
                         cudaFuncAttributeMaxDynamicSharedMemorySize, SM_BYTES);

    reset_kernel<<<1, 256>>>();
    obs_kernel<<<(BATCH * TLEN) / 8, 256>>>(inputs);
    dim3 grid(JG, BG);
    hmm_kernel<<<grid, 256, SM_BYTES>>>(A, Bm, I);
    finalize1_kernel<<<96, 256>>>(A, rf, rt);
    finalize2_kernel<<<1, 32>>>(out);
}

// round 10
// speedup vs baseline: 2.1974x; 1.0624x over previous
#include <cuda_runtime.h>
#include <math.h>

#define S     610
#define SP    640          // padded state dim
#define E     126
#define BATCH 32
#define TLEN  2048
#define NREG  5000
#define JG    20           // column groups (20*32 = 640)
#define BG    4            // batch groups (4*8 = 32)
#define NB    8            // batches per block
#define BMP   127          // Bm smem row stride (odd -> conflict-free gather)
#define S0F   0.0079f      // fixed scale anchor (~typical z)

typedef unsigned long long ull;

// ---------------- persistent device scratch ----------------
__device__ float  g_alpha[4][BATCH][SP];     // 4-deep ring of scaled alpha (padding cols written 0 every step)
__device__ float  g_p[TLEN][BATCH][JG];      // per-step per-colgroup partial sums of alpha (s_t = sum over jg)
__device__ double g_part[84];                // finalize partials
__device__ int    g_flag[BG][JG * 32];       // per-block progress flags, 128B apart
__device__ int    g_obsT[TLEN * BATCH];      // obs transposed [t][b]

// ---------------- helpers ----------------
__device__ __forceinline__ float warp_sum(float v) {
    v += __shfl_xor_sync(0xffffffffu, v, 16);
    v += __shfl_xor_sync(0xffffffffu, v, 8);
    v += __shfl_xor_sync(0xffffffffu, v, 4);
    v += __shfl_xor_sync(0xffffffffu, v, 2);
    v += __shfl_xor_sync(0xffffffffu, v, 1);
    return v;
}
__device__ __forceinline__ ull ffma2(ull a, ull b, ull c) {
    ull d;
    asm("fma.rn.f32x2 %0, %1, %2, %3;" : "=l"(d) : "l"(a), "l"(b), "l"(c));
    return d;
}
__device__ __forceinline__ ull packf2(float lo, float hi) {
    ull r;
    asm("mov.b64 %0, {%1, %2};" : "=l"(r) : "f"(lo), "f"(hi));
    return r;
}
__device__ __forceinline__ int ld_acq_s32(const int* p) {
    int v;
    asm volatile("ld.acquire.gpu.global.s32 %0, [%1];" : "=r"(v) : "l"(p));
    return v;
}
__device__ __forceinline__ void st_rel_s32(int* p, int v) {
    asm volatile("st.release.gpu.global.s32 [%0], %1;" :: "l"(p), "r"(v));
}
__device__ __forceinline__ float ld_cg_f32(const float* p) {
    float v;
    asm volatile("ld.global.cg.f32 %0, [%1];" : "=f"(v) : "l"(p));
    return v;
}
__device__ __forceinline__ void st_cg_f32(float* p, float v) {
    asm volatile("st.global.cg.f32 [%0], %1;" :: "l"(p), "f"(v));
}
__device__ __forceinline__ void cp_async16(unsigned sa, const void* ga) {
    asm volatile("cp.async.cg.shared.global [%0], [%1], 16;" :: "r"(sa), "l"(ga) : "memory");
}
__device__ __forceinline__ void cp_async_wait_all() {
    asm volatile("cp.async.commit_group;\n\tcp.async.wait_group 0;" ::: "memory");
}

// ---------------- kernel 1: reset flags (graph-replay safety) ----------------
__global__ void reset_kernel() {
    for (int k = threadIdx.x; k < BG * JG * 32; k += 256) ((int*)g_flag)[k] = 0;
}

// ---------------- kernel 2: one-hot -> index (transposed) ----------------
__global__ void obs_kernel(const float* __restrict__ inputs) {
    int wid = threadIdx.x >> 5, lane = threadIdx.x & 31;
    int idx = blockIdx.x * 8 + wid;             // one warp per (b,t) row
    if (idx >= BATCH * TLEN) return;
    const float* row = inputs + (size_t)idx * E;
    int best = 0;
#pragma unroll
    for (int m = 0; m < 4; m++) {
        int e = lane + 32 * m;
        if (e < E && row[e] > 0.5f) best = e;
    }
#pragma unroll
    for (int d = 16; d; d >>= 1)
        best = max(best, __shfl_xor_sync(0xffffffffu, best, d));
    if (lane == 0) {
        int b = idx / TLEN, t = idx % TLEN;
        g_obsT[t * BATCH + b] = best;
    }
}

// ---------------- kernel 3: persistent scaled forward ----------------
// grid (20, 4), 256 threads. Warp w: batch bg*8+w for output, k-slice [80w, 80w+80) for compute.
// A slice in registers (40 ull). smem:
//   als  ulonglong2[8*160] @     0  (20480)  per-warp alpha slices [w][bb][q]
//   Bms  float[32*127]     @ 20480  (16256)
//   pacc float2[8*8*32]    @ 36736  (16384)  k-partials [w][bb][lane]
#define SM_BYTES 53120

__global__ void __launch_bounds__(256, 1)
hmm_kernel(const float* __restrict__ Ag, const float* __restrict__ Bmg,
           const float* __restrict__ Ig) {
    extern __shared__ char sm[];
    ulonglong2* als = (ulonglong2*)(sm);
    float*      Bms = (float*)(sm + 20480);
    float2*     pacc = (float2*)(sm + 36736);

    const int tid  = threadIdx.x;
    const int w    = tid >> 5, lane = tid & 31;
    const int jg   = blockIdx.x;        // 0..19
    const int bg   = blockIdx.y;        // 0..3
    const int b    = bg * NB + w;       // output batch of this warp
    const int col0 = jg * 32;
    const int col  = col0 + lane;
    const int k0w  = 80 * w;            // this warp's k-slice base
    const int jg0  = (5 * w) >> 1;      // first producer col-group of this slice

    const unsigned als_sa = (unsigned)__cvta_generic_to_shared(als);

    // ---- prologue: A k-slice x col into registers (zero-padded) ----
    ull au[40];
#pragma unroll
    for (int q = 0; q < 20; q++) {
        int k0 = k0w + 4 * q;
        float x0 = 0.f, x1 = 0.f, x2 = 0.f, x3 = 0.f;
        if (col < S) {
            if (k0     < S) x0 = Ag[(size_t)(k0    ) * S + col];
            if (k0 + 1 < S) x1 = Ag[(size_t)(k0 + 1) * S + col];
            if (k0 + 2 < S) x2 = Ag[(size_t)(k0 + 2) * S + col];
            if (k0 + 3 < S) x3 = Ag[(size_t)(k0 + 3) * S + col];
        }
        au[2 * q]     = packf2(x0, x1);
        au[2 * q + 1] = packf2(x2, x3);
    }
    for (int idx = tid; idx < 32 * BMP; idx += 256) {
        int j = idx / BMP, e = idx % BMP;
        int c = col0 + j;
        Bms[idx] = (c < S && e < E) ? Bmg[(size_t)c * E + e] : 0.f;
    }
    __syncthreads();

    // ---- t = 0: alpha0 = I * em0 ----
    {
        int o = g_obsT[0 * BATCH + b];
        float iv = (col < S) ? Ig[col] : 0.f;
        float v0 = iv * Bms[lane * BMP + o];
        st_cg_f32(&g_alpha[0][b][col], v0);
        float zp = warp_sum(v0);
        if (lane == 0) st_cg_f32(&g_p[0][b][jg], zp);
    }
    __syncthreads();
    if (tid == 0) st_rel_s32(&g_flag[bg][jg * 32], 1);

    const int* const myflags = &g_flag[bg][0];

    for (int t = 1; t < TLEN; ++t) {
        const int ring = t & 3, prev = (t - 1) & 3;

        // ---- per-warp poll: only this slice's 3 producers ----
        {
            const int* fp = (lane < 3) ? &myflags[(jg0 + lane) * 32] : (const int*)0;
            while (true) {
                int f = (lane < 3) ? ld_acq_s32(fp) : 0x7fffffff;
                if (__all_sync(0xffffffffu, f >= t)) break;
            }
        }

        // s_{t-2} partials (visibility guaranteed transitively by the acquire above)
        float pv = 0.f;
        if (t >= 2 && lane < 20) pv = ld_cg_f32(&g_p[t - 2][b][lane]);
        int o = g_obsT[t * BATCH + b];

        // ---- per-warp stage: 160 x 16B of alpha_{t-1} (8 batches x 20 k-quads) ----
#pragma unroll
        for (int j = 0; j < 5; j++) {
            int idx = j * 32 + lane;            // 0..159 = bb*20 + q
            int bb = idx / 20, q = idx - bb * 20;
            cp_async16(als_sa + (unsigned)(w * 160 + idx) * 16u,
                       &g_alpha[prev][bg * NB + bb][k0w + 4 * q]);
        }
        cp_async_wait_all();
        __syncwarp();

        // ---- k-slice matvec: A in registers, alpha via smem broadcast ----
        ull acc[NB];
#pragma unroll
        for (int bb = 0; bb < NB; bb++) acc[bb] = 0ull;
#pragma unroll
        for (int q = 0; q < 20; q++) {
#pragma unroll
            for (int bb = 0; bb < NB; bb++) {
                ulonglong2 av = als[w * 160 + bb * 20 + q];
                acc[bb] = ffma2(av.x, au[2 * q],     acc[bb]);
                acc[bb] = ffma2(av.y, au[2 * q + 1], acc[bb]);
            }
        }
#pragma unroll
        for (int bb = 0; bb < NB; bb++) {
            float2 p;
            asm("mov.b64 {%0, %1}, %2;" : "=f"(p.x), "=f"(p.y) : "l"(acc[bb]));
            pacc[(w * NB + bb) * 32 + lane] = p;
        }

        // stale normalizer: d_t = rsqrt(s_{t-2} * S0)
        float s2 = warp_sum(pv);
        float rz = (t >= 2) ? rsqrtf(s2 * S0F) : 1.0f;

        __syncthreads();

        // ---- output: reduce k-partials, scale, store alpha_t + s_t partial ----
        {
            float ssum = 0.f;
#pragma unroll
            for (int w2 = 0; w2 < 8; w2++) {
                float2 pp = pacc[(w2 * NB + w) * 32 + lane];
                ssum += pp.x + pp.y;
            }
            float val = ssum * Bms[lane * BMP + o] * rz;
            st_cg_f32(&g_alpha[ring][b][col], val);
            float zp = warp_sum(val);
            if (lane == 0) st_cg_f32(&g_p[t][b][jg], zp);
        }
        __syncthreads();
        if (tid == 0) st_rel_s32(&g_flag[bg][jg * 32], t + 1);
    }
}

// ---------------- kernel 4a: parallel loglik + regularizer partials ----------------
// blocks 0..63: (b, t-half); blocks 64..83: regularizer
__global__ void finalize1_kernel(const float* __restrict__ Ag,
                                 const int* __restrict__ rf,
                                 const int* __restrict__ rt) {
    __shared__ double red[256];
    int blk = blockIdx.x, tid = threadIdx.x;
    double acc = 0.0;
    if (blk < 64) {
        int b = blk & 31, t0 = (blk >> 5) * 1024;
        for (int i = tid; i < 1024; i += 256) {
            int t = t0 + i;
            const float4* row = (const float4*)&g_p[t][b][0];  // 20 floats, 16B-aligned
            float4 r0 = row[0], r1 = row[1], r2 = row[2], r3 = row[3], r4 = row[4];
            float s = ((r0.x + r0.y) + (r0.z + r0.w)) + ((r1.x + r1.y) + (r1.z + r1.w))
                    + ((r2.x + r2.y) + (r2.z + r2.w)) + ((r3.x + r3.y) + (r3.z + r3.w))
                    + ((r4.x + r4.y) + (r4.z + r4.w));
            if (t <= TLEN - 3) {
                float d = rsqrtf(s * S0F);       // the divisor applied at step t+2
                acc -= (double)logf(d);
            } else if (t == TLEN - 1) {
                acc += (double)logf(s);
            } // t == TLEN-2 contributes nothing
        }
    } else {
        int idx = (blk - 64) * 256 + tid;
        if (idx < NREG) {
            float a = Ag[(size_t)rf[idx] * S + rt[idx]];
            acc = (double)log1pf(-a);
        }
    }
    red[tid] = acc;
    __syncthreads();
    for (int st = 128; st; st >>= 1) {
        if (tid < st) red[tid] += red[tid + st];
        __syncthreads();
    }
    if (tid == 0) g_part[blk] = red[0];
}

// ---------------- kernel 4b: combine ----------------
__global__ void finalize2_kernel(float* __restrict__ out) {
    if (threadIdx.x == 0) {
        double ll = 0.0, rg = 0.0;
        for (int i = 0; i < 64; i++) ll += g_part[i];
        for (int i = 64; i < 84; i++) rg += g_part[i];
        double loss = -(ll / (double)BATCH) - 4.0 * (rg / (double)NREG);
        out[0] = (float)loss;
    }
}

// ---------------- launcher ----------------
extern "C" void kernel_launch(void* const* d_in, const int* in_sizes, int n_in,
                              void* d_out, int out_size) {
    const float* inputs = (const float*)d_in[0];   // [32,2048,126]
    const float* A      = (const float*)d_in[1];   // [610,610]
    const float* Bm     = (const float*)d_in[2];   // [610,126]
    const float* I      = (const float*)d_in[3];   // [610]
    const int*   rf     = (const int*)d_in[4];     // [5000]
    const int*   rt     = (const int*)d_in[5];     // [5000]
    float* out = (float*)d_out;

    cudaFuncSetAttribute(hmm_kernel,
                         cudaFuncAttributeMaxDynamicSharedMemorySize, SM_BYTES);

    reset_kernel<<<1, 256>>>();
    obs_kernel<<<(BATCH * TLEN) / 8, 256>>>(inputs);
    dim3 grid(JG, BG);
    hmm_kernel<<<grid, 256, SM_BYTES>>>(A, Bm, I);
    finalize1_kernel<<<84, 256>>>(A, rf, rt);
    finalize2_kernel<<<1, 32>>>(out);
}

// round 11
// speedup vs baseline: 2.8695x; 1.3058x over previous
#include <cuda_runtime.h>
#include <math.h>

#define S     610
#define SP    640          // padded state dim
#define E     126
#define BATCH 32
#define TLEN  2048
#define NREG  5000
#define JG    20           // column groups (20*32 = 640)
#define BG    4            // batch groups (4*8 = 32)
#define NB    8            // batches per block
#define BMP   127          // Bm smem row stride (odd -> conflict-free gather)
#define S0F   0.0079f      // fixed scale anchor

typedef unsigned long long ull;

// ---------------- persistent device scratch ----------------
__device__ float  g_alpha[4][BATCH][SP];   // 4-deep ring, 2 LSBs of each float = epoch tag
__device__ float  g_p[TLEN][BATCH][JG];    // per-step per-colgroup partial sums (strictly > 0)
__device__ double g_part[84];              // finalize partials
__device__ int    g_obsT[TLEN * BATCH];    // obs transposed [t][b]

// ---------------- helpers ----------------
__device__ __forceinline__ float warp_sum(float v) {
    v += __shfl_xor_sync(0xffffffffu, v, 16);
    v += __shfl_xor_sync(0xffffffffu, v, 8);
    v += __shfl_xor_sync(0xffffffffu, v, 4);
    v += __shfl_xor_sync(0xffffffffu, v, 2);
    v += __shfl_xor_sync(0xffffffffu, v, 1);
    return v;
}
__device__ __forceinline__ ull ffma2(ull a, ull b, ull c) {
    ull d;
    asm("fma.rn.f32x2 %0, %1, %2, %3;" : "=l"(d) : "l"(a), "l"(b), "l"(c));
    return d;
}
__device__ __forceinline__ ull packf2(float lo, float hi) {
    ull r;
    asm("mov.b64 %0, {%1, %2};" : "=l"(r) : "f"(lo), "f"(hi));
    return r;
}
__device__ __forceinline__ float ld_cg_f32(const float* p) {
    float v;
    asm volatile("ld.global.cg.f32 %0, [%1];" : "=f"(v) : "l"(p));
    return v;
}
__device__ __forceinline__ void st_cg_f32(float* p, float v) {
    asm volatile("st.global.cg.f32 [%0], %1;" :: "l"(p), "f"(v));
}
__device__ __forceinline__ float4 ld_cg_f128(const float4* p) {
    float4 v;
    asm volatile("ld.global.cg.v4.f32 {%0,%1,%2,%3}, [%4];"
                 : "=f"(v.x), "=f"(v.y), "=f"(v.z), "=f"(v.w) : "l"(p));
    return v;
}
__device__ __forceinline__ void cp_async16(unsigned sa, const void* ga) {
    asm volatile("cp.async.cg.shared.global [%0], [%1], 16;" :: "r"(sa), "l"(ga) : "memory");
}
__device__ __forceinline__ void cp_commit() {
    asm volatile("cp.async.commit_group;" ::: "memory");
}
__device__ __forceinline__ void cp_wait0() {
    asm volatile("cp.async.wait_group 0;" ::: "memory");
}

// ---------------- kernel 1: arm the alpha ring with tag-3 denormals ----------------
// 0x00000003: value ~4e-45 (never produced), tag bits = 3. Consumers' first
// expectation of tag 3 for a slot is step t-1=12, by which time the slot has been
// freshly rewritten at t=0,4,8 (enforced by earlier tag checks) -> no stale accept.
__global__ void reset_kernel() {
    int i = blockIdx.x * 256 + threadIdx.x;
    unsigned* p = (unsigned*)g_alpha;
#pragma unroll
    for (int k = 0; k < 4; k++) p[i + k * 80 * 256] = 3u;
}

// ---------------- kernel 2: one-hot -> index (transposed) ----------------
__global__ void obs_kernel(const float* __restrict__ inputs) {
    int wid = threadIdx.x >> 5, lane = threadIdx.x & 31;
    int idx = blockIdx.x * 8 + wid;             // one warp per (b,t) row
    if (idx >= BATCH * TLEN) return;
    const float* row = inputs + (size_t)idx * E;
    int best = 0;
#pragma unroll
    for (int m = 0; m < 4; m++) {
        int e = lane + 32 * m;
        if (e < E && row[e] > 0.5f) best = e;
    }
#pragma unroll
    for (int d = 16; d; d >>= 1)
        best = max(best, __shfl_xor_sync(0xffffffffu, best, d));
    if (lane == 0) {
        int b = idx / TLEN, t = idx % TLEN;
        g_obsT[t * BATCH + b] = best;
    }
}

// ---------------- kernel 3: persistent scaled forward ----------------
// grid (20, 4), 256 threads. Warp w: output batch bg*8+w; compute k-slice [80w, 80w+80).
// A slice in registers (40 ull). smem (double-buffered by step parity):
//   als[2]  ulonglong2[8*160] @ 0 / 20480      alpha_{t-1} slices [w][bb*20+q]
//   Bms     float[32*127]     @ 40960 (16256)
//   pacc[2] float2[8*8*32]    @ 57344 / 73728  k-partials [w][bb][lane]
#define SM_BYTES 90112

__global__ void __launch_bounds__(256, 1)
hmm_kernel(const float* __restrict__ Ag, const float* __restrict__ Bmg,
           const float* __restrict__ Ig) {
    extern __shared__ char sm[];
    float* Bms = (float*)(sm + 40960);

    const int tid  = threadIdx.x;
    const int w    = tid >> 5, lane = tid & 31;
    const int jg   = blockIdx.x;        // 0..19
    const int bg   = blockIdx.y;        // 0..3
    const int b    = bg * NB + w;       // output batch of this warp
    const int col0 = jg * 32;
    const int col  = col0 + lane;
    const int k0w  = 80 * w;            // this warp's k-slice base

    // ---- prologue: A k-slice x col into registers (zero-padded) ----
    ull au[40];
#pragma unroll
    for (int q = 0; q < 20; q++) {
        int k0 = k0w + 4 * q;
        float x0 = 0.f, x1 = 0.f, x2 = 0.f, x3 = 0.f;
        if (col < S) {
            if (k0     < S) x0 = Ag[(size_t)(k0    ) * S + col];
            if (k0 + 1 < S) x1 = Ag[(size_t)(k0 + 1) * S + col];
            if (k0 + 2 < S) x2 = Ag[(size_t)(k0 + 2) * S + col];
            if (k0 + 3 < S) x3 = Ag[(size_t)(k0 + 3) * S + col];
        }
        au[2 * q]     = packf2(x0, x1);
        au[2 * q + 1] = packf2(x2, x3);
    }
    for (int idx = tid; idx < 32 * BMP; idx += 256) {
        int j = idx / BMP, e = idx % BMP;
        int c = col0 + j;
        Bms[idx] = (c < S && e < E) ? Bmg[(size_t)c * E + e] : 0.f;
    }
    __syncthreads();

    // ---- t = 0: alpha0 = I * em0, tag 0 ----
    float val_prev;
    {
        int o = g_obsT[0 * BATCH + b];
        float iv = (col < S) ? Ig[col] : 0.f;
        float v0 = iv * Bms[lane * BMP + o];
        unsigned bits = __float_as_uint(v0) & ~3u;       // tag = (0>>2)&3 = 0
        val_prev = __uint_as_float(bits);
        st_cg_f32(&g_alpha[0][b][col], val_prev);
    }

    for (int t = 1; t < TLEN; ++t) {
        const int ring = t & 3, prev = (t - 1) & 3;
        const unsigned tag_r = (unsigned)((t - 1) >> 2) & 3u;
        const unsigned tag_w = (unsigned)(t >> 2) & 3u;
        ulonglong2* als  = (ulonglong2*)(sm + ((t & 1) ? 20480 : 0));
        float2*     pacc = (float2*)(sm + ((t & 1) ? 73728 : 57344));
        const unsigned als_sa = (unsigned)__cvta_generic_to_shared(als);

        // (1) issue cp.async for alpha_{t-1} slice (160 x 16B per warp)
#pragma unroll
        for (int j = 0; j < 5; j++) {
            int idx = j * 32 + lane;
            int bb = idx / 20, q = idx - bb * 20;
            cp_async16(als_sa + (unsigned)(w * 160 + idx) * 16u,
                       &g_alpha[prev][bg * NB + bb][k0w + 4 * q]);
        }
        cp_commit();

        // (2) deferred normalizer partial of step t-1 (overlaps cp.async wait)
        {
            float zp = warp_sum(val_prev);
            if (lane == 0) st_cg_f32(&g_p[t - 1][b][jg], zp);
        }

        // (3) prime s_{t-2} read + fast-path rz (overlaps cp.async wait)
        const float* gp = &g_p[(t >= 2 ? t - 2 : 0)][b][lane];
        float pre = 1.f, rz = 1.f;
        bool rz_done = (t < 2);
        if (t >= 2) {
            if (lane < 20) pre = ld_cg_f32(gp);
            if (__all_sync(0xffffffffu, (lane >= 20) | (pre != 0.f))) {
                float pv = (lane < 20) ? pre : 0.f;
                rz = rsqrtf(warp_sum(pv) * S0F);
                rz_done = true;
            }
        }
        int o = g_obsT[t * BATCH + b];

        // (4) wait + tag-validate staged alpha; retry until fresh
        for (;;) {
            cp_wait0();
            __syncwarp();
            bool ok = true;
#pragma unroll
            for (int j = 0; j < 5; j++) {
                uint4 u = ((const uint4*)als)[w * 160 + j * 32 + lane];
                ok &= ((u.x & 3u) == tag_r) & ((u.y & 3u) == tag_r)
                    & ((u.z & 3u) == tag_r) & ((u.w & 3u) == tag_r);
            }
            if (__all_sync(0xffffffffu, ok)) break;
#pragma unroll
            for (int j = 0; j < 5; j++) {
                int idx = j * 32 + lane;
                int bb = idx / 20, q = idx - bb * 20;
                cp_async16(als_sa + (unsigned)(w * 160 + idx) * 16u,
                           &g_alpha[prev][bg * NB + bb][k0w + 4 * q]);
            }
            cp_commit();
        }

        // (5) k-slice matvec: A in registers, alpha via smem broadcast
        ull acc[NB];
#pragma unroll
        for (int bb = 0; bb < NB; bb++) acc[bb] = 0ull;
#pragma unroll
        for (int q = 0; q < 20; q++) {
#pragma unroll
            for (int bb = 0; bb < NB; bb++) {
                ulonglong2 av = als[w * 160 + bb * 20 + q];
                acc[bb] = ffma2(av.x, au[2 * q],     acc[bb]);
                acc[bb] = ffma2(av.y, au[2 * q + 1], acc[bb]);
            }
        }
#pragma unroll
        for (int bb = 0; bb < NB; bb++) {
            float2 p;
            asm("mov.b64 {%0, %1}, %2;" : "=f"(p.x), "=f"(p.y) : "l"(acc[bb]));
            pacc[(w * NB + bb) * 32 + lane] = p;
        }
        __syncthreads();

        // (6) slow-path rz (rare: s_{t-2} not yet visible at prime time)
        if (!rz_done) {
            for (;;) {
                if (__all_sync(0xffffffffu, (lane >= 20) | (pre != 0.f))) break;
                if (lane < 20) pre = ld_cg_f32(gp);
            }
            float pv = (lane < 20) ? pre : 0.f;
            rz = rsqrtf(warp_sum(pv) * S0F);
        }

        // (7) reduce k-partials, scale, embed tag, store alpha_t
        {
            float ssum = 0.f;
#pragma unroll
            for (int w2 = 0; w2 < 8; w2++) {
                float2 pp = pacc[(w2 * NB + w) * 32 + lane];
                ssum += pp.x + pp.y;
            }
            float val = ssum * Bms[lane * BMP + o] * rz;
            unsigned vb = (__float_as_uint(val) & ~3u) | tag_w;
            float vt = __uint_as_float(vb);
            st_cg_f32(&g_alpha[ring][b][col], vt);
            val_prev = vt;
        }
    }

    // final normalizer partial for t = TLEN-1
    {
        float zp = warp_sum(val_prev);
        if (lane == 0) st_cg_f32(&g_p[TLEN - 1][b][jg], zp);
    }
}

// ---------------- kernel 4a: parallel loglik + regularizer partials ----------------
__global__ void finalize1_kernel(const float* __restrict__ Ag,
                                 const int* __restrict__ rf,
                                 const int* __restrict__ rt) {
    __shared__ double red[256];
    int blk = blockIdx.x, tid = threadIdx.x;
    double acc = 0.0;
    if (blk < 64) {
        int b = blk & 31, t0 = (blk >> 5) * 1024;
        for (int i = tid; i < 1024; i += 256) {
            int t = t0 + i;
            const float4* row = (const float4*)&g_p[t][b][0];  // 20 floats, 16B-aligned
            float4 r0 = row[0], r1 = row[1], r2 = row[2], r3 = row[3], r4 = row[4];
            float s = ((r0.x + r0.y) + (r0.z + r0.w)) + ((r1.x + r1.y) + (r1.z + r1.w))
                    + ((r2.x + r2.y) + (r2.z + r2.w)) + ((r3.x + r3.y) + (r3.z + r3.w))
                    + ((r4.x + r4.y) + (r4.z + r4.w));
            if (t <= TLEN - 3) {
                acc -= (double)logf(rsqrtf(s * S0F));  // divisor applied at step t+2
            } else if (t == TLEN - 1) {
                acc += (double)logf(s);
            }
        }
    } else {
        int idx = (blk - 64) * 256 + tid;
        if (idx < NREG) {
            float a = Ag[(size_t)rf[idx] * S + rt[idx]];
            acc = (double)log1pf(-a);
        }
    }
    red[tid] = acc;
    __syncthreads();
    for (int st = 128; st; st >>= 1) {
        if (tid < st) red[tid] += red[tid + st];
        __syncthreads();
    }
    if (tid == 0) g_part[blk] = red[0];
}

// ---------------- kernel 4b: combine ----------------
__global__ void finalize2_kernel(float* __restrict__ out) {
    if (threadIdx.x == 0) {
        double ll = 0.0, rg = 0.0;
        for (int i = 0; i < 64; i++) ll += g_part[i];
        for (int i = 64; i < 84; i++) rg += g_part[i];
        double loss = -(ll / (double)BATCH) - 4.0 * (rg / (double)NREG);
        out[0] = (float)loss;
    }
}

// ---------------- launcher ----------------
extern "C" void kernel_launch(void* const* d_in, const int* in_sizes, int n_in,
                              void* d_out, int out_size) {
    const float* inputs = (const float*)d_in[0];   // [32,2048,126]
    const float* A      = (const float*)d_in[1];   // [610,610]
    const float* Bm     = (const float*)d_in[2];   // [610,126]
    const float* I      = (const float*)d_in[3];   // [610]
    const int*   rf     = (const int*)d_in[4];     // [5000]
    const int*   rt     = (const int*)d_in[5];     // [5000]
    float* out = (float*)d_out;

    cudaFuncSetAttribute(hmm_kernel,
                         cudaFuncAttributeMaxDynamicSharedMemorySize, SM_BYTES);

    reset_kernel<<<80, 256>>>();
    obs_kernel<<<(BATCH * TLEN) / 8, 256>>>(inputs);
    dim3 grid(JG, BG);
    hmm_kernel<<<grid, 256, SM_BYTES>>>(A, Bm, I);
    finalize1_kernel<<<84, 256>>>(A, rf, rt);
    finalize2_kernel<<<1, 32>>>(out);
}